// round 10
// baseline (speedup 1.0000x reference)
#include <cuda_runtime.h>

#define BB 4
#define RR 64
#define FF 1024
#define DD 128
#define FT 32          // k2 f-tile width
#define NFT (FF/FT)    // 32 f-tiles

// ---------------- device scratch (static; no allocations) ----------------
__device__ float g_fproj[BB*FF*DD];
__device__ float g_rproj[BB*RR*DD];
__device__ float g_wd[DD];
__device__ float g_escore[BB*RR*FF];
__device__ float g_sums_part[NFT*BB*RR];
__device__ float g_msg_part[NFT*BB*RR*DD];

// ---------------- kernel 1: projections -----------------------------------
// 16-row x 64-col tiles, 256 threads, 1r x 4c per thread.
// blocks 0..511  : f_proj  (rowtile = blk>>1 over 4096 rows, chalf = blk&1)
// blocks 512..543: r_proj + b1 (256 rows)
// block  544     : w_d column sums
#define K1_SMEM ((DD*64 + DD*17) * 4)

__global__ __launch_bounds__(256)
void k1_proj(const float* __restrict__ robot,
             const float* __restrict__ frontier,
             const float* __restrict__ W1,
             const float* __restrict__ b1) {
    extern __shared__ float sm[];
    float* w_s = sm;               // [k][c]  128 x 64 (column half)
    float* x_s = sm + DD*64;       // [k][r]  128 x 17
    const int t   = threadIdx.x;
    const int blk = blockIdx.x;

    if (blk >= 544) {
        if (t < DD) {
            float s = 0.f;
            #pragma unroll 8
            for (int k = 0; k < DD; k++) s += W1[(2*DD + k)*DD + t];
            g_wd[t] = s;
        }
        return;
    }

    const float* Wbase;
    const float* X;
    float* O;
    int chalf;
    bool add_b1;
    if (blk < 512) {
        int rowtile = blk >> 1;  chalf = blk & 1;
        Wbase = W1 + DD*DD;                       // W1f
        X = frontier + (size_t)rowtile*16*DD;     // rows are (b,f) flattened
        O = g_fproj  + (size_t)rowtile*16*DD;
        add_b1 = false;
    } else {
        int idx = blk - 512;
        int rowtile = idx >> 1;  chalf = idx & 1;
        Wbase = W1;                               // W1r
        X = robot   + (size_t)rowtile*16*DD;      // rows are (b,r) flattened
        O = g_rproj + (size_t)rowtile*16*DD;
        add_b1 = true;
    }

    // load W column-half: w_s[k][c] = W[k*128 + chalf*64 + c]
    for (int i = t; i < DD*64; i += 256) {
        int k = i >> 6, c = i & 63;
        w_s[i] = Wbase[k*DD + chalf*64 + c];
    }
    // load X transposed: x_s[k][r]
    for (int i = t; i < 16*DD; i += 256) {
        int r = i >> 7, k = i & 127;
        x_s[k*17 + r] = X[i];
    }
    __syncthreads();

    const int cg = t & 15, r = t >> 4;     // r in 0..15
    const int c0 = cg*4;
    float acc0 = 0.f, acc1 = 0.f, acc2 = 0.f, acc3 = 0.f;

    #pragma unroll 8
    for (int k = 0; k < DD; k++) {
        float  xv = x_s[k*17 + r];
        float4 w4 = *(const float4*)&w_s[k*64 + c0];
        acc0 = fmaf(xv, w4.x, acc0);
        acc1 = fmaf(xv, w4.y, acc1);
        acc2 = fmaf(xv, w4.z, acc2);
        acc3 = fmaf(xv, w4.w, acc3);
    }

    if (add_b1) {
        const float* bp = b1 + chalf*64 + c0;
        acc0 += bp[0]; acc1 += bp[1]; acc2 += bp[2]; acc3 += bp[3];
    }

    *(float4*)&O[r*DD + chalf*64 + c0] = make_float4(acc0, acc1, acc2, acc3);
}

// ---------------- kernel 2: fused scores + exp + softmax partials + message partials
// grid 512: b = x>>7, ftile = (x>>2)&31, rq = x&3 (16 robots, 32 f per block)
// 256 threads, ~49KB smem -> 4 blocks/SM.
// NOTE: fp_s stride is 34 (EVEN) so float2 reads at d*34+f0 stay 8B-aligned.
#define K2_SMEM_FLOATS (DD*17 + DD*34 + 16*33 + FT*132 + FT*17 + 2*DD + 16*16)
#define K2_SMEM (K2_SMEM_FLOATS * 4)

__global__ __launch_bounds__(256)
void k2_main(const float* __restrict__ frontier,
             const float* __restrict__ geo,
             const float* __restrict__ W2,
             const float* __restrict__ b2) {
    extern __shared__ float sm[];
    float*  rp_s  = sm;                      // [d][r]  128 x 17
    float*  fp_s  = rp_s  + DD*17;           // [d][f]  128 x 34  (even stride!)
    float*  geo_s = fp_s  + DD*34;           // [r][f]   16 x 33
    float*  fr_s  = geo_s + 16*33;           // [f][d]   32 x 132
    float*  e_s   = fr_s  + FT*132;          // [f][r]   32 x 17
    float2* wz_s  = (float2*)(e_s + FT*17);  // 128 x {wd, w2}
    float*  ps_s  = e_s + FT*17 + 2*DD;      // 16 x 16

    const int t = threadIdx.x;
    const int x = blockIdx.x;
    const int b     = x >> 7;
    const int ftile = (x >> 2) & 31;
    const int rbase = (x & 3) * 16;
    const int fbase = ftile * FT;

    const float* RP = g_rproj + (size_t)(b*RR + rbase)*DD;
    for (int i = t; i < 16*DD; i += 256) { int r = i >> 7, d = i & 127; rp_s[d*17 + r] = RP[i]; }
    const float* FP = g_fproj + (size_t)(b*FF + fbase)*DD;
    for (int i = t; i < FT*DD; i += 256) { int f = i >> 7, d = i & 127; fp_s[d*34 + f] = FP[i]; }
    const float* FR = frontier + (size_t)(b*FF + fbase)*DD;
    for (int i = t; i < FT*DD; i += 256) { int f = i >> 7, d = i & 127; fr_s[f*132 + d] = FR[i]; }
    const float* G = geo + (size_t)(b*RR + rbase)*FF + fbase;
    for (int i = t; i < 16*FT; i += 256) { int r = i >> 5, f = i & 31; geo_s[r*33 + f] = G[r*FF + f]; }
    if (t < DD) wz_s[t] = make_float2(g_wd[t], W2[t]);
    __syncthreads();

    // ---- phase A: scores, 1r x 2f per thread over 16r x 32f ----
    const int fx = t & 15, r = t >> 4;       // r in 0..15
    const int f0 = fx*2;

    const float g0 = geo_s[r*33 + f0];
    const float g1 = geo_s[r*33 + f0 + 1];
    float a0 = 0.f, a1 = 0.f;

    #pragma unroll 8
    for (int d = 0; d < DD; d++) {
        float  rpv = rp_s[d*17 + r];
        float2 fp2 = *(const float2*)&fp_s[d*34 + f0];   // aligned: even*even + even
        float2 wz  = wz_s[d];
        float v0 = rpv + fp2.x;
        float v1 = rpv + fp2.y;
        v0 = fmaf(g0, wz.x, v0);
        v1 = fmaf(g1, wz.x, v1);
        v0 = fmaxf(v0, 0.f);
        v1 = fmaxf(v1, 0.f);
        a0 = fmaf(v0, wz.y, a0);
        a1 = fmaf(v1, wz.y, a1);
    }

    const float b2v = b2[0];
    float e0 = __expf(fmaxf(a0 + b2v, 0.f));   // scores >= 0, small: exact softmax w/o max-sub
    float e1 = __expf(fmaxf(a1 + b2v, 0.f));
    e_s[(f0+0)*17 + r] = e0;
    e_s[(f0+1)*17 + r] = e1;
    ps_s[r*16 + fx] = e0 + e1;

    float* EO = g_escore + (size_t)(b*RR + rbase + r)*FF + fbase;
    *(float2*)&EO[f0] = make_float2(e0, e1);
    __syncthreads();

    if (t < 16) {
        float s = 0.f;
        #pragma unroll
        for (int q = 0; q < 16; q++) s += ps_s[t*16 + q];
        g_sums_part[ftile*(BB*RR) + b*RR + rbase + t] = s;
    }

    // ---- phase B: partial messages, 1r x 8d per thread over 16r x 128d ----
    const int dg = t & 15, r2 = t >> 4;
    const int d0 = dg*8;
    float m0=0.f,m1=0.f,m2=0.f,m3=0.f,m4=0.f,m5=0.f,m6=0.f,m7=0.f;

    #pragma unroll 4
    for (int f = 0; f < FT; f++) {
        float  ev = e_s[f*17 + r2];
        float4 fA = *(const float4*)&fr_s[f*132 + d0];
        float4 fB = *(const float4*)&fr_s[f*132 + d0 + 4];
        m0 = fmaf(ev, fA.x, m0);
        m1 = fmaf(ev, fA.y, m1);
        m2 = fmaf(ev, fA.z, m2);
        m3 = fmaf(ev, fA.w, m3);
        m4 = fmaf(ev, fB.x, m4);
        m5 = fmaf(ev, fB.y, m5);
        m6 = fmaf(ev, fB.z, m6);
        m7 = fmaf(ev, fB.w, m7);
    }

    float* MO = g_msg_part + (size_t)(ftile*(BB*RR) + b*RR + rbase + r2)*DD;
    *(float4*)&MO[d0]     = make_float4(m0, m1, m2, m3);
    *(float4*)&MO[d0 + 4] = make_float4(m4, m5, m6, m7);
}

// ---------------- kernel 3: normalize + outputs ----------------------------
// grid = 256 (one per (b,r)), 128 threads
__global__ __launch_bounds__(128)
void k3_out(const float* __restrict__ robot,
            const float* __restrict__ Wn,
            const float* __restrict__ bn,
            float* __restrict__ out) {
    __shared__ float comb[2*DD];
    const int br = blockIdx.x;
    const int t  = threadIdx.x;

    float s = 0.f;
    #pragma unroll 8
    for (int p = 0; p < NFT; p++) s += g_sums_part[p*(BB*RR) + br];
    const float inv = 1.0f / s;

    float mm = 0.f;
    #pragma unroll 8
    for (int p = 0; p < NFT; p++) mm += g_msg_part[(size_t)(p*(BB*RR) + br)*DD + t];
    comb[DD + t] = mm * inv;
    comb[t]      = robot[(size_t)br*DD + t];

    const float* E  = g_escore + (size_t)br*FF;
    float*       ew = out + (size_t)BB*RR*DD + (size_t)br*FF;
    #pragma unroll
    for (int k = 0; k < FF/DD; k++) ew[k*DD + t] = E[k*DD + t] * inv;
    __syncthreads();

    float acc = bn[t];
    #pragma unroll 8
    for (int k = 0; k < 2*DD; k++) acc = fmaf(comb[k], Wn[k*DD + t], acc);
    out[(size_t)br*DD + t] = fmaxf(acc, 0.f);
}

// ---------------- launch ----------------------------------------------------
extern "C" void kernel_launch(void* const* d_in, const int* in_sizes, int n_in,
                              void* d_out, int out_size) {
    const float* robot    = (const float*)d_in[0];
    const float* frontier = (const float*)d_in[1];
    const float* geo      = (const float*)d_in[2];
    const float* W1       = (const float*)d_in[3];
    const float* b1       = (const float*)d_in[4];
    const float* W2       = (const float*)d_in[5];
    const float* b2       = (const float*)d_in[6];
    const float* Wn       = (const float*)d_in[7];
    const float* bn       = (const float*)d_in[8];
    float* out = (float*)d_out;

    cudaFuncSetAttribute(k1_proj, cudaFuncAttributeMaxDynamicSharedMemorySize, K1_SMEM);
    cudaFuncSetAttribute(k2_main, cudaFuncAttributeMaxDynamicSharedMemorySize, K2_SMEM);

    k1_proj<<<545, 256, K1_SMEM>>>(robot, frontier, W1, b1);
    k2_main<<<512, 256, K2_SMEM>>>(frontier, geo, W2, b2);
    k3_out<<<256, 128>>>(robot, Wn, bn, out);
}

// round 14
// speedup vs baseline: 1.3951x; 1.3951x over previous
#include <cuda_runtime.h>

#define BB 4
#define RR 64
#define FF 1024
#define DD 128
#define FT 64          // k2 f-tile width
#define NFT (FF/FT)    // 16 f-tiles

// ---------------- device scratch (static; no allocations) ----------------
__device__ float g_fproj[BB*FF*DD];
__device__ float g_rproj[BB*RR*DD];
__device__ float g_wd[DD];
__device__ float g_escore[BB*RR*FF];
__device__ float g_sums_part[NFT*BB*RR];
__device__ float g_msg_part[NFT*BB*RR*DD];

// ---------------- kernel 1: projections -----------------------------------
// 32-row x 64-col tiles, 256 threads, 2r x 4c per thread.
// Thread map: cg = t>>4 (warp-uniform cols -> W reads broadcast),
//             r  = t&15 (per-lane rows    -> x reads 1 conflict-free phase).
// x_s stride = 34 (32 rows + 2 pad, EVEN so float2 at k*34+r*2 is 8B-aligned).
// blocks 0..255  : f_proj (rowtile = blk>>1 over 4096 rows, chalf = blk&1)
// blocks 256..271: r_proj + b1 (256 rows)
// block  272     : w_d column sums
#define K1_SMEM ((DD*64 + DD*34) * 4)

__global__ __launch_bounds__(256)
void k1_proj(const float* __restrict__ robot,
             const float* __restrict__ frontier,
             const float* __restrict__ W1,
             const float* __restrict__ b1) {
    extern __shared__ float sm[];
    float* w_s = sm;               // [k][c]  128 x 64 (column half)
    float* x_s = sm + DD*64;       // [k][r]  128 x 34 (32 rows + pad)
    const int t   = threadIdx.x;
    const int blk = blockIdx.x;

    if (blk >= 272) {
        if (t < DD) {
            float s = 0.f;
            #pragma unroll 8
            for (int k = 0; k < DD; k++) s += W1[(2*DD + k)*DD + t];
            g_wd[t] = s;
        }
        return;
    }

    const float* Wbase;
    const float* X;
    float* O;
    int chalf;
    bool add_b1;
    if (blk < 256) {
        int rowtile = blk >> 1;  chalf = blk & 1;
        Wbase = W1 + DD*DD;                       // W1f
        X = frontier + (size_t)rowtile*32*DD;     // rows = (b,f) flattened
        O = g_fproj  + (size_t)rowtile*32*DD;
        add_b1 = false;
    } else {
        int idx = blk - 256;
        int rowtile = idx >> 1;  chalf = idx & 1;
        Wbase = W1;                               // W1r
        X = robot   + (size_t)rowtile*32*DD;      // rows = (b,r) flattened
        O = g_rproj + (size_t)rowtile*32*DD;
        add_b1 = true;
    }

    for (int i = t; i < DD*64; i += 256) {
        int k = i >> 6, c = i & 63;
        w_s[i] = Wbase[k*DD + chalf*64 + c];
    }
    for (int i = t; i < 32*DD; i += 256) {
        int r = i >> 7, k = i & 127;
        x_s[k*34 + r] = X[i];
    }
    __syncthreads();

    const int cg = t >> 4, r = t & 15;   // cg warp-uniform-ish, r per-lane
    const int c0 = cg*4, r0 = r*2;
    float a00=0.f,a01=0.f,a02=0.f,a03=0.f;
    float a10=0.f,a11=0.f,a12=0.f,a13=0.f;

    #pragma unroll 8
    for (int k = 0; k < DD; k++) {
        float2 x2 = *(const float2*)&x_s[k*34 + r0];   // 16 lanes consecutive: 1 phase
        float4 w4 = *(const float4*)&w_s[k*64 + c0];   // 2 distinct per warp: broadcast
        a00 = fmaf(x2.x, w4.x, a00);
        a01 = fmaf(x2.x, w4.y, a01);
        a02 = fmaf(x2.x, w4.z, a02);
        a03 = fmaf(x2.x, w4.w, a03);
        a10 = fmaf(x2.y, w4.x, a10);
        a11 = fmaf(x2.y, w4.y, a11);
        a12 = fmaf(x2.y, w4.z, a12);
        a13 = fmaf(x2.y, w4.w, a13);
    }

    if (add_b1) {
        const float* bp = b1 + chalf*64 + c0;
        float b0 = bp[0], bB = bp[1], b2c = bp[2], b3 = bp[3];
        a00 += b0; a01 += bB; a02 += b2c; a03 += b3;
        a10 += b0; a11 += bB; a12 += b2c; a13 += b3;
    }

    *(float4*)&O[(r0+0)*DD + chalf*64 + c0] = make_float4(a00, a01, a02, a03);
    *(float4*)&O[(r0+1)*DD + chalf*64 + c0] = make_float4(a10, a11, a12, a13);
}

// ---------------- kernel 2: fused scores + exp + softmax partials + message partials
// grid 256: b = x>>6, ftile = (x>>2)&15, rq = x&3 (16 robots, 64 f per block)
// 256 threads, ~88KB smem -> 2 blocks/SM.
// Thread map phase A: fx = t>>4 (warp-uniform f -> fp4 broadcast), r = t&15.
//            phase B: dg = t>>4 (warp-uniform d -> fr4 broadcast), r2 = t&15.
#define K2_SMEM_FLOATS (DD*17 + DD*68 + 16*65 + FT*132 + FT*17 + 2*DD + 16*16)
#define K2_SMEM (K2_SMEM_FLOATS * 4)

__global__ __launch_bounds__(256)
void k2_main(const float* __restrict__ frontier,
             const float* __restrict__ geo,
             const float* __restrict__ W2,
             const float* __restrict__ b2) {
    extern __shared__ float sm[];
    float*  rp_s  = sm;                      // [d][r]  128 x 17 (scalar reads)
    float*  fp_s  = rp_s  + DD*17;           // [d][f]  128 x 68 (even: aligned float4)
    float*  geo_s = fp_s  + DD*68;           // [r][f]   16 x 65
    float*  fr_s  = geo_s + 16*65;           // [f][d]   64 x 132
    float*  e_s   = fr_s  + FT*132;          // [f][r]   64 x 17
    float2* wz_s  = (float2*)(e_s + FT*17);  // 128 x {wd, w2}
    float*  ps_s  = e_s + FT*17 + 2*DD;      // 16 x 16

    const int t = threadIdx.x;
    const int x = blockIdx.x;
    const int b     = x >> 6;
    const int ftile = (x >> 2) & 15;
    const int rbase = (x & 3) * 16;
    const int fbase = ftile * FT;

    const float* RP = g_rproj + (size_t)(b*RR + rbase)*DD;
    for (int i = t; i < 16*DD; i += 256) { int r = i >> 7, d = i & 127; rp_s[d*17 + r] = RP[i]; }
    const float* FP = g_fproj + (size_t)(b*FF + fbase)*DD;
    for (int i = t; i < FT*DD; i += 256) { int f = i >> 7, d = i & 127; fp_s[d*68 + f] = FP[i]; }
    const float* FR = frontier + (size_t)(b*FF + fbase)*DD;
    for (int i = t; i < FT*DD; i += 256) { int f = i >> 7, d = i & 127; fr_s[f*132 + d] = FR[i]; }
    const float* G = geo + (size_t)(b*RR + rbase)*FF + fbase;
    for (int i = t; i < 16*FT; i += 256) { int r = i >> 6, f = i & 63; geo_s[r*65 + f] = G[r*FF + f]; }
    if (t < DD) wz_s[t] = make_float2(g_wd[t], W2[t]);
    __syncthreads();

    // ---- phase A: scores, 1r x 4f per thread over 16r x 64f ----
    const int fx = t >> 4, r = t & 15;
    const int f0 = fx*4;

    const float g0 = geo_s[r*65 + f0];
    const float g1 = geo_s[r*65 + f0 + 1];
    const float g2 = geo_s[r*65 + f0 + 2];
    const float g3 = geo_s[r*65 + f0 + 3];
    float a0 = 0.f, a1 = 0.f, a2 = 0.f, a3 = 0.f;

    #pragma unroll 8
    for (int d = 0; d < DD; d++) {
        float  rpv = rp_s[d*17 + r];                    // 16 consecutive lanes: 1 phase
        float4 fp4 = *(const float4*)&fp_s[d*68 + f0];  // 2 distinct per warp: broadcast
        float2 wz  = wz_s[d];                           // broadcast
        float v0 = rpv + fp4.x;
        float v1 = rpv + fp4.y;
        float v2 = rpv + fp4.z;
        float v3 = rpv + fp4.w;
        v0 = fmaf(g0, wz.x, v0);
        v1 = fmaf(g1, wz.x, v1);
        v2 = fmaf(g2, wz.x, v2);
        v3 = fmaf(g3, wz.x, v3);
        v0 = fmaxf(v0, 0.f);
        v1 = fmaxf(v1, 0.f);
        v2 = fmaxf(v2, 0.f);
        v3 = fmaxf(v3, 0.f);
        a0 = fmaf(v0, wz.y, a0);
        a1 = fmaf(v1, wz.y, a1);
        a2 = fmaf(v2, wz.y, a2);
        a3 = fmaf(v3, wz.y, a3);
    }

    const float b2v = b2[0];
    float e0 = __expf(fmaxf(a0 + b2v, 0.f));   // scores >= 0, small: exact softmax w/o max-sub
    float e1 = __expf(fmaxf(a1 + b2v, 0.f));
    float e2 = __expf(fmaxf(a2 + b2v, 0.f));
    float e3 = __expf(fmaxf(a3 + b2v, 0.f));
    e_s[(f0+0)*17 + r] = e0;
    e_s[(f0+1)*17 + r] = e1;
    e_s[(f0+2)*17 + r] = e2;
    e_s[(f0+3)*17 + r] = e3;
    ps_s[r*16 + fx] = e0 + e1 + e2 + e3;

    float* EO = g_escore + (size_t)(b*RR + rbase + r)*FF + fbase;
    *(float4*)&EO[f0] = make_float4(e0, e1, e2, e3);
    __syncthreads();

    if (t < 16) {
        float s = 0.f;
        #pragma unroll
        for (int q = 0; q < 16; q++) s += ps_s[t*16 + q];
        g_sums_part[ftile*(BB*RR) + b*RR + rbase + t] = s;
    }

    // ---- phase B: partial messages, 1r x 8d per thread over 16r x 128d ----
    const int dg = t >> 4, r2 = t & 15;
    const int d0 = dg*8;
    float m0=0.f,m1=0.f,m2=0.f,m3=0.f,m4=0.f,m5=0.f,m6=0.f,m7=0.f;

    #pragma unroll 4
    for (int f = 0; f < FT; f++) {
        float  ev = e_s[f*17 + r2];                        // 16 consecutive lanes
        float4 fA = *(const float4*)&fr_s[f*132 + d0];     // 2 distinct: broadcast
        float4 fB = *(const float4*)&fr_s[f*132 + d0 + 4];
        m0 = fmaf(ev, fA.x, m0);
        m1 = fmaf(ev, fA.y, m1);
        m2 = fmaf(ev, fA.z, m2);
        m3 = fmaf(ev, fA.w, m3);
        m4 = fmaf(ev, fB.x, m4);
        m5 = fmaf(ev, fB.y, m5);
        m6 = fmaf(ev, fB.z, m6);
        m7 = fmaf(ev, fB.w, m7);
    }

    float* MO = g_msg_part + (size_t)(ftile*(BB*RR) + b*RR + rbase + r2)*DD;
    *(float4*)&MO[d0]     = make_float4(m0, m1, m2, m3);
    *(float4*)&MO[d0 + 4] = make_float4(m4, m5, m6, m7);
}

// ---------------- kernel 3: normalize + outputs ----------------------------
// grid = 256 (one per (b,r)), 128 threads
__global__ __launch_bounds__(128)
void k3_out(const float* __restrict__ robot,
            const float* __restrict__ Wn,
            const float* __restrict__ bn,
            float* __restrict__ out) {
    __shared__ float comb[2*DD];
    const int br = blockIdx.x;
    const int t  = threadIdx.x;

    float s = 0.f;
    #pragma unroll
    for (int p = 0; p < NFT; p++) s += g_sums_part[p*(BB*RR) + br];
    const float inv = 1.0f / s;

    float mm = 0.f;
    #pragma unroll
    for (int p = 0; p < NFT; p++) mm += g_msg_part[(size_t)(p*(BB*RR) + br)*DD + t];
    comb[DD + t] = mm * inv;
    comb[t]      = robot[(size_t)br*DD + t];

    const float* E  = g_escore + (size_t)br*FF;
    float*       ew = out + (size_t)BB*RR*DD + (size_t)br*FF;
    #pragma unroll
    for (int k = 0; k < FF/DD; k++) ew[k*DD + t] = E[k*DD + t] * inv;
    __syncthreads();

    float acc = bn[t];
    #pragma unroll 8
    for (int k = 0; k < 2*DD; k++) acc = fmaf(comb[k], Wn[k*DD + t], acc);
    out[(size_t)br*DD + t] = fmaxf(acc, 0.f);
}

// ---------------- launch ----------------------------------------------------
extern "C" void kernel_launch(void* const* d_in, const int* in_sizes, int n_in,
                              void* d_out, int out_size) {
    const float* robot    = (const float*)d_in[0];
    const float* frontier = (const float*)d_in[1];
    const float* geo      = (const float*)d_in[2];
    const float* W1       = (const float*)d_in[3];
    const float* b1       = (const float*)d_in[4];
    const float* W2       = (const float*)d_in[5];
    const float* b2       = (const float*)d_in[6];
    const float* Wn       = (const float*)d_in[7];
    const float* bn       = (const float*)d_in[8];
    float* out = (float*)d_out;

    cudaFuncSetAttribute(k1_proj, cudaFuncAttributeMaxDynamicSharedMemorySize, K1_SMEM);
    cudaFuncSetAttribute(k2_main, cudaFuncAttributeMaxDynamicSharedMemorySize, K2_SMEM);

    k1_proj<<<273, 256, K1_SMEM>>>(robot, frontier, W1, b1);
    k2_main<<<256, 256, K2_SMEM>>>(frontier, geo, W2, b2);
    k3_out<<<256, 128>>>(robot, Wn, bn, out);
}